// round 9
// baseline (speedup 1.0000x reference)
#include <cuda_runtime.h>
#include <cuda_bf16.h>
#include <math.h>

#define SS   128
#define BB   32
#define NHID 1024
#define NH   16
#define HDIM 64
#define VV   32000
#define NBLK 148

#define W_U32 16384     // 2 x 8192 u32 = 64 KB W ping-pong (NT8=16)
#define A_U32 4096      // 2 x 2048 u32 = 16 KB A ping-pong

// ---------------- scratch (device globals; no allocation) ----------------
__device__ float g_keys[(SS + 1) * BB * NHID];
__device__ float g_vals[(SS + 1) * BB * NHID];
__device__ float g_part[16 * BB * 4096];                 // KS*B*N max (KS<=16)
__device__ float g_p1[SS * BB * 1024];
__device__ float g_p2[SS * BB * 4096];
__device__ unsigned g_cnt;
__device__ unsigned g_gen;
__device__ unsigned g_ticket;

// fragment-ordered, pre-split weights: per (n8,k16,lane) uint4 = (b0h,b1h,b0l,b1l)
__device__ __align__(16) unsigned g_qwp  [1024 * 2048];
__device__ __align__(16) unsigned g_intwp[4096 * 4096];
__device__ __align__(16) unsigned g_finwp[3072 * 4096];
__device__ __align__(16) unsigned g_decwp[VV * 1024];
// row-major packed (hi,lo) activations
__device__ __align__(16) unsigned g_embp [SS * BB * 1024];
__device__ __align__(16) unsigned g_hidp [BB * 1024];
__device__ __align__(16) unsigned g_qp   [BB * 1024];
__device__ __align__(16) unsigned g_attnp[BB * 1024];
__device__ __align__(16) unsigned g_interp[BB * 4096];
__device__ __align__(16) unsigned g_spack[SS * BB * 1024];

// ---------------- helpers ----------------
__device__ __forceinline__ unsigned packsplit(float x) {
    __nv_bfloat16 h = __float2bfloat16(x);
    __nv_bfloat16 l = __float2bfloat16(x - __bfloat162float(h));
    return (unsigned)__bfloat16_as_ushort(h) | ((unsigned)__bfloat16_as_ushort(l) << 16);
}
__device__ __forceinline__ unsigned prmt(unsigned a, unsigned b, unsigned s) {
    unsigned d; asm("prmt.b32 %0,%1,%2,%3;" : "=r"(d) : "r"(a), "r"(b), "r"(s)); return d;
}
__device__ __forceinline__ void mma16816(float* c, const unsigned* a, unsigned b0, unsigned b1) {
    asm volatile(
        "mma.sync.aligned.m16n8k16.row.col.f32.bf16.bf16.f32 "
        "{%0,%1,%2,%3}, {%4,%5,%6,%7}, {%8,%9}, {%0,%1,%2,%3};"
        : "+f"(c[0]), "+f"(c[1]), "+f"(c[2]), "+f"(c[3])
        : "r"(a[0]), "r"(a[1]), "r"(a[2]), "r"(a[3]), "r"(b0), "r"(b1));
}
__device__ __forceinline__ void cp16(unsigned dst, const void* src) {
    asm volatile("cp.async.cg.shared.global [%0], [%1], 16;" :: "r"(dst), "l"(src));
}
__device__ __forceinline__ void cp_commit() { asm volatile("cp.async.commit_group;"); }
template<int N_> __device__ __forceinline__ void cp_wait() {
    asm volatile("cp.async.wait_group %0;" :: "n"(N_));
}

// ---------------- grid barrier (nanosleep backoff; releaser resets ticket) ----------------
__device__ __forceinline__ void gridbar() {
    __syncthreads();
    if (threadIdx.x == 0) {
        volatile unsigned* gen = &g_gen;
        unsigned g = *gen;
        __threadfence();
        if (atomicAdd(&g_cnt, 1u) == NBLK - 1) {
            g_cnt = 0;
            g_ticket = 0;
            __threadfence();
            *gen = g + 1;
        } else {
            while (*gen == g) { __nanosleep(64); }
        }
        __threadfence();
    }
    __syncthreads();
}

struct SmemL { float buf[4096]; float red[32]; float qs[1024]; float sc[16][132]; };

__device__ __forceinline__ float block_reduce(float v, float* red) {
    __syncthreads();
    int tid = threadIdx.x;
    #pragma unroll
    for (int o = 16; o > 0; o >>= 1) v += __shfl_xor_sync(~0u, v, o);
    if ((tid & 31) == 0) red[tid >> 5] = v;
    __syncthreads();
    if (tid < 16) {
        v = red[tid];
        #pragma unroll
        for (int o = 8; o > 0; o >>= 1) v += __shfl_xor_sync(0xffff, v, o);
        if (tid == 0) red[0] = v;
    }
    __syncthreads();
    return red[0];
}

// ---------------- GEMM machinery (NT8=16, dynamic task stealing) ----------------
__device__ __forceinline__ const uint4* stage_addr(const unsigned* const* segs, int segshift,
                                                   unsigned kmask, int xstride, int k0,
                                                   int sm_m, int sm_j) {
    const unsigned* seg = segs[k0 >> segshift];
    return (const uint4*)(seg + (size_t)sm_m * xstride + (k0 & kmask) + sm_j * 4);
}

// issue one 64-k W chunk (NT8=16 -> 32 KB) via cp.async
__device__ __forceinline__ void issue_w(const unsigned* __restrict__ Wf, int K16tot,
                                        int n8_0, int k16_0, unsigned dst_smem) {
    const int tid = threadIdx.x;
    #pragma unroll
    for (int f = 0; f < 4; f++) {
        int id = f * 512 + tid;
        int kk = id >> 9, rest = id & 511;
        const unsigned* src = Wf + (((size_t)(n8_0 + (rest >> 5)) * K16tot + k16_0 + kk) * 32
                                    + (rest & 31)) * 4;
        cp16(dst_smem + id * 16, src);
    }
    cp_commit();
}

__device__ __forceinline__ void prefetch_w(unsigned* dyn, const unsigned* __restrict__ Wf,
                                           int K16tot, int woff, int N, int K, int KS) {
    int ntasks = (N >> 7) * KS;
    int task = blockIdx.x;
    if (task >= ntasks) return;
    int nt = task / KS, ks = task - nt * KS;
    unsigned wsm = (unsigned)__cvta_generic_to_shared(dyn);
    issue_w(Wf, K16tot, nt << 4, woff + ((ks * (K / KS)) >> 4), wsm);
}

// dynamic task loop; first task = blockIdx (chunk0 pre-issued), steals via g_ticket.
__device__ void gemm_mma(unsigned* dyn, const unsigned* const* segs, int segshift, int xstride,
                         const unsigned* __restrict__ Wf, int K16tot, int woff,
                         int N, int K, int KS) {
    const int ntasks = (N >> 7) * KS;
    int task = blockIdx.x;
    if (task >= ntasks) return;
    __shared__ int s_next;
    unsigned* Wbuf = dyn;
    unsigned* Abuf = dyn + W_U32;
    const int Kc = K / KS;
    const int nc = Kc >> 6;
    const unsigned kmask = (1u << segshift) - 1u;
    const int tid = threadIdx.x;
    const int warp = tid >> 5, lane = tid & 31;
    const int t = lane & 3, gq = lane >> 2;
    const unsigned wsm = (unsigned)__cvta_generic_to_shared(Wbuf);

    // A staging role
    const int sm_m = tid >> 4, sm_j = tid & 15;
    const int s_row = sm_m & 15, s_g = s_row & 7, s_rh = s_row >> 3, s_mt = sm_m >> 4;
    const int s_k16 = sm_j >> 2, s_kb = (sm_j & 3) << 2;
    const int s_t0 = (s_kb >> 1) & 3;
    const int s_w = s_rh + ((s_kb >> 3) << 1);
    const int s_base = ((s_k16 * 2 + s_mt) * 32 + s_g * 4 + s_t0) * 4 + s_w;

    uint4 v = *stage_addr(segs, segshift, kmask, xstride, (task % KS) * Kc, sm_m, sm_j);
    int cc = 0;

    for (;;) {
        const int nt = task / KS, ks = task - nt * KS;
        const int n8_0 = nt << 4;
        const int k0b = ks * Kc;
        float acc[2][4];
        #pragma unroll
        for (int mt = 0; mt < 2; mt++)
            #pragma unroll
            for (int e = 0; e < 4; e++) acc[mt][e] = 0.f;

        int next_task = ntasks;
        for (int c = 0; c < nc; c++) {
            const int p = cc & 1; cc++;
            unsigned* abuf = Abuf + p * 2048;
            abuf[s_base]            = prmt(v.x, v.y, 0x5410);
            abuf[s_base + 4]        = prmt(v.z, v.w, 0x5410);
            abuf[1024 + s_base]     = prmt(v.x, v.y, 0x7632);
            abuf[1024 + s_base + 4] = prmt(v.z, v.w, 0x7632);
            bool issued = false;
            if (c + 1 < nc) {
                issue_w(Wf, K16tot, n8_0, woff + ((k0b + (c + 1) * 64) >> 4),
                        wsm + (p ^ 1) * (W_U32 * 2));
                v = *stage_addr(segs, segshift, kmask, xstride, k0b + (c + 1) * 64, sm_m, sm_j);
                issued = true;
            } else {
                if (tid == 0) s_next = (int)atomicAdd(&g_ticket, 1u) + NBLK;
                __syncthreads();
                next_task = s_next;
                if (next_task < ntasks) {
                    int nt2 = next_task / KS, ks2 = next_task - nt2 * KS;
                    issue_w(Wf, K16tot, nt2 << 4, woff + ((ks2 * Kc) >> 4),
                            wsm + (p ^ 1) * (W_U32 * 2));
                    v = *stage_addr(segs, segshift, kmask, xstride, ks2 * Kc, sm_m, sm_j);
                    issued = true;
                }
            }
            if (issued) cp_wait<1>(); else cp_wait<0>();
            __syncthreads();
            const unsigned* wb = Wbuf + p * (W_U32 / 2);
            #pragma unroll
            for (int kk = 0; kk < 4; kk++) {
                unsigned ah[2][4], al[2][4];
                #pragma unroll
                for (int mt = 0; mt < 2; mt++) {
                    *(uint4*)ah[mt] = *(const uint4*)&abuf[((kk * 2 + mt) * 32 + lane) * 4];
                    *(uint4*)al[mt] = *(const uint4*)&abuf[1024 + ((kk * 2 + mt) * 32 + lane) * 4];
                }
                const uint4 q = *(const uint4*)&wb[((kk * 16 + warp) * 32 + lane) * 4];
                #pragma unroll
                for (int mt = 0; mt < 2; mt++) {
                    mma16816(acc[mt], ah[mt], q.x, q.y);
                    mma16816(acc[mt], ah[mt], q.z, q.w);
                    mma16816(acc[mt], al[mt], q.x, q.y);
                }
            }
            __syncthreads();
        }
        float* dst = g_part + (size_t)ks * BB * N;
        const int n0w = (nt << 7) + (warp << 3);
        #pragma unroll
        for (int mt = 0; mt < 2; mt++) {
            int m = mt * 16 + gq;
            int n = n0w + t * 2;
            *(float2*)&dst[(size_t)m * N + n]       = make_float2(acc[mt][0], acc[mt][1]);
            *(float2*)&dst[(size_t)(m + 8) * N + n] = make_float2(acc[mt][2], acc[mt][3]);
        }
        if (next_task >= ntasks) break;
        task = next_task;
    }
}

// ---------------- LN (+ReLU), float4 path ----------------
__device__ void ln_phase(SmemL& sm, const float* __restrict__ pre, const float* __restrict__ bias,
                         const float* __restrict__ gam, const float* __restrict__ bet,
                         int N, int KS, int mode, int i, float* __restrict__ out_states) {
    int b = blockIdx.x;
    if (b >= BB) return;
    int tid = threadIdx.x;
    const int N4 = N >> 2;
    float s = 0.f, ss = 0.f;
    for (int j4 = tid; j4 < N4; j4 += 512) {
        float4 v = pre ? ((const float4*)pre)[b * N4 + j4] : ((const float4*)bias)[j4];
        for (int ks = 0; ks < KS; ks++) {
            float4 p = ((const float4*)g_part)[((size_t)ks * BB + b) * N4 + j4];
            v.x += p.x; v.y += p.y; v.z += p.z; v.w += p.w;
        }
        ((float4*)sm.buf)[j4] = v;
        s += v.x + v.y + v.z + v.w;
        ss += v.x * v.x + v.y * v.y + v.z * v.z + v.w * v.w;
    }
    float mu = block_reduce(s, sm.red) / (float)N;
    float var = block_reduce(ss, sm.red) / (float)N - mu * mu;
    float rs = rsqrtf(var + 1e-5f);
    for (int j4 = tid; j4 < N4; j4 += 512) {
        float4 v = ((const float4*)sm.buf)[j4];
        float4 gm = ((const float4*)gam)[j4];
        float4 bt = ((const float4*)bet)[j4];
        float4 y;
        y.x = fmaxf((v.x - mu) * rs * gm.x + bt.x, 0.f);
        y.y = fmaxf((v.y - mu) * rs * gm.y + bt.y, 0.f);
        y.z = fmaxf((v.z - mu) * rs * gm.z + bt.z, 0.f);
        y.w = fmaxf((v.w - mu) * rs * gm.w + bt.w, 0.f);
        if (mode == 1) {
            uint4 p = make_uint4(packsplit(y.x), packsplit(y.y), packsplit(y.z), packsplit(y.w));
            ((uint4*)g_interp)[b * 1024 + j4] = p;
        } else {
            if (j4 < 256) {
                ((float4*)(g_keys + ((size_t)(i + 1) * BB + b) * NHID))[j4] = y;
            } else if (j4 < 512) {
                ((float4*)(g_vals + ((size_t)(i + 1) * BB + b) * NHID))[j4 - 256] = y;
            } else {
                int jj4 = j4 - 512;
                uint4 p = make_uint4(packsplit(y.x), packsplit(y.y), packsplit(y.z), packsplit(y.w));
                ((uint4*)g_hidp)[b * 256 + jj4] = p;
                ((uint4*)g_spack)[((size_t)i * BB + b) * 256 + jj4] = p;
                ((float4*)(out_states + ((size_t)(i + 1) * BB + b) * NHID))[jj4] = y;
            }
        }
    }
}

// ---------------- fused LN(q) + attention ----------------
__device__ void ln_attn_phase(SmemL& sm, const float* __restrict__ pre,
                              const float* __restrict__ gam, const float* __restrict__ bet, int i) {
    int b = blockIdx.x;
    if (b >= BB) return;
    int tid = threadIdx.x;
    float s = 0.f, ss = 0.f;
    if (tid < 256) {
        int j4 = tid;
        float4 v = ((const float4*)pre)[b * 256 + j4];
        #pragma unroll
        for (int ks = 0; ks < 16; ks++) {
            float4 p = ((const float4*)g_part)[((size_t)ks * BB + b) * 256 + j4];
            v.x += p.x; v.y += p.y; v.z += p.z; v.w += p.w;
        }
        ((float4*)sm.buf)[j4] = v;
        s = v.x + v.y + v.z + v.w;
        ss = v.x * v.x + v.y * v.y + v.z * v.z + v.w * v.w;
    }
    float mu = block_reduce(s, sm.red) / 1024.f;
    float var = block_reduce(ss, sm.red) / 1024.f - mu * mu;
    float rs = rsqrtf(var + 1e-5f);
    if (tid < 256) {
        int j4 = tid;
        float4 v = ((const float4*)sm.buf)[j4];
        float4 gm = ((const float4*)gam)[j4];
        float4 bt = ((const float4*)bet)[j4];
        float4 y;
        y.x = fmaxf((v.x - mu) * rs * gm.x + bt.x, 0.f);
        y.y = fmaxf((v.y - mu) * rs * gm.y + bt.y, 0.f);
        y.z = fmaxf((v.z - mu) * rs * gm.z + bt.z, 0.f);
        y.w = fmaxf((v.w - mu) * rs * gm.w + bt.w, 0.f);
        ((float4*)sm.qs)[j4] = y;
        uint4 p = make_uint4(packsplit(y.x), packsplit(y.y), packsplit(y.z), packsplit(y.w));
        ((uint4*)g_qp)[b * 256 + j4] = p;
    }
    __syncthreads();

    int len = i + 1;
    int hd = tid >> 5, lane = tid & 31;
    {
        float sv[4];
        float mx = -1e30f;
        #pragma unroll
        for (int r = 0; r < 4; r++) {
            int c = lane + 32 * r;
            float d = -1e30f;
            if (c < len) {
                const float* kp = g_keys + ((size_t)c * BB + b) * NHID + hd * HDIM;
                float a2 = 0.f;
                #pragma unroll
                for (int h = 0; h < HDIM; h += 4) {
                    float4 kv = *(const float4*)&kp[h];
                    a2 += kv.x * sm.qs[hd * HDIM + h]     + kv.y * sm.qs[hd * HDIM + h + 1]
                        + kv.z * sm.qs[hd * HDIM + h + 2] + kv.w * sm.qs[hd * HDIM + h + 3];
                }
                d = a2 * 0.125f;
            }
            sv[r] = d;
            mx = fmaxf(mx, d);
        }
        #pragma unroll
        for (int o = 16; o > 0; o >>= 1) mx = fmaxf(mx, __shfl_xor_sync(~0u, mx, o));
        float sum = 0.f;
        #pragma unroll
        for (int r = 0; r < 4; r++) {
            int c = lane + 32 * r;
            float e = (c < len) ? __expf(sv[r] - mx) : 0.f;
            sv[r] = e; sum += e;
        }
        #pragma unroll
        for (int o = 16; o > 0; o >>= 1) sum += __shfl_xor_sync(~0u, sum, o);
        float inv = 1.f / sum;
        #pragma unroll
        for (int r = 0; r < 4; r++) {
            int c = lane + 32 * r;
            if (c < len) sm.sc[hd][c] = sv[r] * inv;
        }
    }
    __syncthreads();

    for (int idx = tid; idx < 1024; idx += 512) {
        int h2 = idx >> 6, h = idx & 63;
        float a = 0.f;
        const float* vp = g_vals + b * NHID + h2 * HDIM + h;
        #pragma unroll 4
        for (int c = 0; c < len; c++) a += sm.sc[h2][c] * vp[(size_t)c * BB * NHID];
        g_attnp[b * 1024 + idx] = packsplit(a);
    }
}

// ---------------- persistent sequence kernel ----------------
__global__ void __launch_bounds__(512, 1) k_seq(
    const float* __restrict__ qn_g,  const float* __restrict__ qn_b,
    const float* __restrict__ intn_g,const float* __restrict__ intn_b,
    const float* __restrict__ fin_b, const float* __restrict__ fn_g,
    const float* __restrict__ fn_b,  float* __restrict__ out_states)
{
    extern __shared__ __align__(16) unsigned dyn[];
    SmemL& sml = *reinterpret_cast<SmemL*>(dyn + W_U32 + A_U32);

    prefetch_w(dyn, g_qwp, 128, 64, 1024, 1024, 16);

    for (int i = 0; i < SS; i++) {
        {   // GEMM1: hidden @ q_w[:,1024:]^T  (N=1024, K=1024, KS=16 -> 128 tasks)
            const unsigned* segs[4] = { g_hidp, g_hidp, g_hidp, g_hidp };
            gemm_mma(dyn, segs, 10, 1024, g_qwp, 128, 64, 1024, 1024, 16);
        }
        prefetch_w(dyn, g_intwp, 256, 64, 4096, 3072, 8);
        gridbar();
        ln_attn_phase(sml, g_p1 + (size_t)i * BB * 1024, qn_g, qn_b, i);
        gridbar();
        {   // GEMM2: [q|attn|hidden] @ int_w[:,1024:]^T (N=4096, K=3072, KS=8 -> 256 tasks)
            const unsigned* segs[4] = { g_qp, g_attnp, g_hidp, g_hidp };
            gemm_mma(dyn, segs, 10, 1024, g_intwp, 256, 64, 4096, 3072, 8);
        }
        prefetch_w(dyn, g_finwp, 256, 0, 3072, 4096, 8);
        gridbar();
        ln_phase(sml, g_p2 + (size_t)i * BB * 4096, 0, intn_g, intn_b, 4096, 8, 1, i, out_states);
        gridbar();
        {   // GEMM3: inter @ fin_w^T (N=3072, K=4096, KS=8 -> 192 tasks)
            const unsigned* segs[4] = { g_interp, g_interp, g_interp, g_interp };
            gemm_mma(dyn, segs, 12, 4096, g_finwp, 256, 0, 3072, 4096, 8);
        }
        prefetch_w(dyn, g_qwp, 128, 64, 1024, 1024, 16);
        gridbar();
        ln_phase(sml, 0, fin_b, fn_g, fn_b, 3072, 8, 2, i, out_states);
        gridbar();
    }
}

// ---------------- weight convert (all four in one kernel) ----------------
__device__ __forceinline__ void convert_range(const float* __restrict__ w,
                                              unsigned* __restrict__ wf, int total, int kshift) {
    const int K = 1 << kshift;
    const int halfK = K >> 1;
    const int pairs = total >> 1;
    for (int i = blockIdx.x * 256 + threadIdx.x; i < pairs; i += gridDim.x * 256) {
        int kp = i & (halfK - 1);
        int n  = i >> (kshift - 1);
        int k  = kp << 1;
        unsigned p0 = packsplit(w[((size_t)n << kshift) + k]);
        unsigned p1 = packsplit(w[((size_t)n << kshift) + k + 1]);
        unsigned bh = prmt(p0, p1, 0x5410);
        unsigned bl = prmt(p0, p1, 0x7632);
        int n8 = n >> 3, g = n & 7;
        int k16 = k >> 4, kr = k & 15;
        int j = kr >> 1, t = j & 3, half = j >> 2;
        size_t base = (((size_t)n8 * (K >> 4) + k16) * 32 + g * 4 + t) * 4;
        wf[base + half]     = bh;
        wf[base + 2 + half] = bl;
    }
}
__global__ void k_convert_all(const float* __restrict__ q_w, const float* __restrict__ int_w,
                              const float* __restrict__ fin_w, const float* __restrict__ dec_w) {
    convert_range(q_w,   g_qwp,   1024 * 2048, 11);
    convert_range(int_w, g_intwp, 4096 * 4096, 12);
    convert_range(fin_w, g_finwp, 3072 * 4096, 12);
    convert_range(dec_w, g_decwp, VV * 1024,   10);
}

// ---------------- embedding gather (packed) ----------------
__global__ void k_embed(const int* __restrict__ obs, const float* __restrict__ enc_w) {
    int sb = blockIdx.x;
    int tok = obs[sb];
    const float4* src = (const float4*)(enc_w + (size_t)tok * 1024);
    float4 v = src[threadIdx.x];
    uint4 p = make_uint4(packsplit(v.x), packsplit(v.y), packsplit(v.z), packsplit(v.w));
    ((uint4*)(g_embp + (size_t)sb * 1024))[threadIdx.x] = p;
}

// ---------------- init ----------------
__global__ void k_init(const float* __restrict__ hidden_init,
                       const float* __restrict__ kci,
                       const float* __restrict__ vci,
                       float* __restrict__ out_states) {
    if (blockIdx.x == 0 && threadIdx.x == 0) { g_cnt = 0; g_gen = 0; g_ticket = 0; }
    int idx = blockIdx.x * 256 + threadIdx.x;
    float4 h = ((const float4*)hidden_init)[idx];
    ((float4*)out_states)[idx] = h;
    ((float4*)g_keys)[idx] = ((const float4*)kci)[idx];
    ((float4*)g_vals)[idx] = ((const float4*)vci)[idx];
    uint4 p = make_uint4(packsplit(h.x), packsplit(h.y), packsplit(h.z), packsplit(h.w));
    ((uint4*)g_hidp)[idx] = p;
}

// ---------------- big-M GEMM: out[4096][ld] = A[4096 x 1024] @ Wf^T + bias ----------------
__global__ void __launch_bounds__(512, 1) k_bigmm(const unsigned* __restrict__ A,
                                                  const unsigned* __restrict__ Wf,
                                                  int K16tot, int woff,
                                                  const float* __restrict__ bias,
                                                  float* __restrict__ out, int ldout) {
    const int m0 = blockIdx.x * 128;
    const int n0 = blockIdx.y * 256;
    const int warp = threadIdx.x >> 5, lane = threadIdx.x & 31;
    const int g = lane >> 2, t = lane & 3;
    const int mb = m0 + (warp & 3) * 32;
    const int nb = n0 + (warp >> 2) * 64;
    const int n8b = nb >> 3;

    float acc[2][8][4];
    #pragma unroll
    for (int mt = 0; mt < 2; mt++)
        #pragma unroll
        for (int ni = 0; ni < 8; ni++)
            #pragma unroll
            for (int e = 0; e < 4; e++) acc[mt][ni][e] = 0.f;

    for (int k0 = 0; k0 < 1024; k0 += 16) {
        unsigned ahi[2][4], alo[2][4];
        #pragma unroll
        for (int mt = 0; mt < 2; mt++) {
            const unsigned* x0 = A + (size_t)(mb + mt * 16 + g) * 1024 + k0 + t * 2;
            const unsigned* x8 = x0 + 8 * 1024;
            uint2 p0 = *(const uint2*)x0;
            uint2 p1 = *(const uint2*)x8;
            uint2 p2 = *(const uint2*)(x0 + 8);
            uint2 p3 = *(const uint2*)(x8 + 8);
            ahi[mt][0] = prmt(p0.x, p0.y, 0x5410); alo[mt][0] = prmt(p0.x, p0.y, 0x7632);
            ahi[mt][1] = prmt(p1.x, p1.y, 0x5410); alo[mt][1] = prmt(p1.x, p1.y, 0x7632);
            ahi[mt][2] = prmt(p2.x, p2.y, 0x5410); alo[mt][2] = prmt(p2.x, p2.y, 0x7632);
            ahi[mt][3] = prmt(p3.x, p3.y, 0x5410); alo[mt][3] = prmt(p3.x, p3.y, 0x7632);
        }
        #pragma unroll
        for (int ni = 0; ni < 8; ni++) {
            const uint4 q = *(const uint4*)(Wf + (((size_t)(n8b + ni) * K16tot + woff + (k0 >> 4)) * 32 + lane) * 4);
            #pragma unroll
            for (int mt = 0; mt < 2; mt++) {
                mma16816(acc[mt][ni], ahi[mt], q.x, q.y);
                mma16816(acc[mt][ni], ahi[mt], q.z, q.w);
                mma16816(acc[mt][ni], alo[mt], q.x, q.y);
            }
        }
    }
    #pragma unroll
    for (int mt = 0; mt < 2; mt++) {
        int m = mb + mt * 16 + g;
        #pragma unroll
        for (int ni = 0; ni < 8; ni++) {
            int n = nb + ni * 8 + t * 2;
            float bx = bias[n], by = bias[n + 1];
            *(float2*)&out[(size_t)m * ldout + n]       = make_float2(acc[mt][ni][0] + bx, acc[mt][ni][1] + by);
            *(float2*)&out[(size_t)(m + 8) * ldout + n] = make_float2(acc[mt][ni][2] + bx, acc[mt][ni][3] + by);
        }
    }
}

// ---------------- launch ----------------
extern "C" void kernel_launch(void* const* d_in, const int* in_sizes, int n_in,
                              void* d_out, int out_size) {
    const int*   obs         = (const int*)d_in[0];
    const float* hidden_init = (const float*)d_in[1];
    const float* kci         = (const float*)d_in[2];
    const float* vci         = (const float*)d_in[3];
    const float* enc_w       = (const float*)d_in[4];
    const float* q_w         = (const float*)d_in[5];
    const float* q_b         = (const float*)d_in[6];
    const float* qn_g        = (const float*)d_in[7];
    const float* qn_b        = (const float*)d_in[8];
    const float* int_w       = (const float*)d_in[9];
    const float* int_b       = (const float*)d_in[10];
    const float* intn_g      = (const float*)d_in[11];
    const float* intn_b      = (const float*)d_in[12];
    const float* fin_w       = (const float*)d_in[13];
    const float* fin_b       = (const float*)d_in[14];
    const float* fn_g        = (const float*)d_in[15];
    const float* fn_b        = (const float*)d_in[16];
    const float* dec_w       = (const float*)d_in[17];
    const float* dec_b       = (const float*)d_in[18];

    float* out        = (float*)d_out;
    float* out_states = out + (size_t)SS * BB * VV;

    unsigned* qwp;  cudaGetSymbolAddress((void**)&qwp,  g_qwp);
    unsigned* iwp;  cudaGetSymbolAddress((void**)&iwp,  g_intwp);
    unsigned* dwp;  cudaGetSymbolAddress((void**)&dwp,  g_decwp);
    unsigned* emb;  cudaGetSymbolAddress((void**)&emb,  g_embp);
    unsigned* spk;  cudaGetSymbolAddress((void**)&spk,  g_spack);
    float* p1;      cudaGetSymbolAddress((void**)&p1,   g_p1);
    float* p2;      cudaGetSymbolAddress((void**)&p2,   g_p2);

    const int smem_bytes = (W_U32 + A_U32) * 4 + (int)sizeof(SmemL);
    static int smem_set = 0;
    if (!smem_set) {
        cudaFuncSetAttribute(k_seq, cudaFuncAttributeMaxDynamicSharedMemorySize, smem_bytes);
        smem_set = 1;
    }

    k_convert_all<<<4096, 256>>>(q_w, int_w, fin_w, dec_w);
    k_embed<<<SS * BB, 256>>>(obs, enc_w);
    k_init<<<32, 256>>>(hidden_init, kci, vci, out_states);

    // precompute embedding contributions (bias folded)
    k_bigmm<<<dim3(32, 4),  512>>>(emb, qwp, 128, 0, q_b,   p1, 1024);
    k_bigmm<<<dim3(32, 16), 512>>>(emb, iwp, 256, 0, int_b, p2, 4096);

    k_seq<<<NBLK, 512, smem_bytes>>>(qn_g, qn_b, intn_g, intn_b,
                                     fin_b, fn_g, fn_b, out_states);

    // decoder
    k_bigmm<<<dim3(32, VV / 256), 512>>>(spk, dwp, 64, 0, dec_b, out, VV);
}

// round 10
// speedup vs baseline: 1.1544x; 1.1544x over previous
#include <cuda_runtime.h>
#include <cuda_bf16.h>
#include <math.h>

#define SS   128
#define BB   32
#define NHID 1024
#define NH   16
#define HDIM 64
#define VV   32000
#define NBLK 148

#define W_U32 32768     // 2 x 16384 u32 = 128 KB W ping-pong (max, NT8=32)
#define A_U32 4096      // 2 x 2048 u32  = 16 KB  A ping-pong

// ---------------- scratch (device globals; no allocation) ----------------
__device__ float g_keys[(SS + 1) * BB * NHID];
__device__ float g_vals[(SS + 1) * BB * NHID];
__device__ float g_part[16 * BB * 4096];
__device__ float g_p1[SS * BB * 1024];
__device__ float g_p2[SS * BB * 4096];
__device__ unsigned g_cnt;
__device__ unsigned g_gen;

// fragment-ordered, pre-split weights: per (n8,k16,lane) uint4 = (b0h,b1h,b0l,b1l)
__device__ __align__(16) unsigned g_qwp  [1024 * 2048];
__device__ __align__(16) unsigned g_intwp[4096 * 4096];
__device__ __align__(16) unsigned g_finwp[3072 * 4096];
__device__ __align__(16) unsigned g_decwp[VV * 1024];
// row-major packed (hi,lo) activations
__device__ __align__(16) unsigned g_embp [SS * BB * 1024];
__device__ __align__(16) unsigned g_hidp [BB * 1024];
__device__ __align__(16) unsigned g_qp   [BB * 1024];
__device__ __align__(16) unsigned g_attnp[BB * 1024];
__device__ __align__(16) unsigned g_interp[BB * 4096];
__device__ __align__(16) unsigned g_spack[SS * BB * 1024];

// ---------------- helpers ----------------
__device__ __forceinline__ unsigned packsplit(float x) {
    __nv_bfloat16 h = __float2bfloat16(x);
    __nv_bfloat16 l = __float2bfloat16(x - __bfloat162float(h));
    return (unsigned)__bfloat16_as_ushort(h) | ((unsigned)__bfloat16_as_ushort(l) << 16);
}
__device__ __forceinline__ unsigned prmt(unsigned a, unsigned b, unsigned s) {
    unsigned d; asm("prmt.b32 %0,%1,%2,%3;" : "=r"(d) : "r"(a), "r"(b), "r"(s)); return d;
}
__device__ __forceinline__ void mma16816(float* c, const unsigned* a, unsigned b0, unsigned b1) {
    asm volatile(
        "mma.sync.aligned.m16n8k16.row.col.f32.bf16.bf16.f32 "
        "{%0,%1,%2,%3}, {%4,%5,%6,%7}, {%8,%9}, {%0,%1,%2,%3};"
        : "+f"(c[0]), "+f"(c[1]), "+f"(c[2]), "+f"(c[3])
        : "r"(a[0]), "r"(a[1]), "r"(a[2]), "r"(a[3]), "r"(b0), "r"(b1));
}
__device__ __forceinline__ void cp16(unsigned dst, const void* src) {
    asm volatile("cp.async.cg.shared.global [%0], [%1], 16;" :: "r"(dst), "l"(src));
}
__device__ __forceinline__ void cp_commit() { asm volatile("cp.async.commit_group;"); }
template<int N_> __device__ __forceinline__ void cp_wait() {
    asm volatile("cp.async.wait_group %0;" :: "n"(N_));
}

// ---------------- grid barrier (nanosleep backoff — load-bearing!) ----------------
__device__ __forceinline__ void gridbar() {
    __syncthreads();
    if (threadIdx.x == 0) {
        volatile unsigned* gen = &g_gen;
        unsigned g = *gen;
        __threadfence();
        if (atomicAdd(&g_cnt, 1u) == NBLK - 1) {
            g_cnt = 0;
            __threadfence();
            *gen = g + 1;
        } else {
            while (*gen == g) { __nanosleep(64); }
        }
        __threadfence();
    }
    __syncthreads();
}

struct SmemL { float buf[4096]; float red[32]; float qs[1024]; float sc[16][132]; };

__device__ __forceinline__ float block_reduce(float v, float* red) {
    __syncthreads();
    int tid = threadIdx.x;
    #pragma unroll
    for (int o = 16; o > 0; o >>= 1) v += __shfl_xor_sync(~0u, v, o);
    if ((tid & 31) == 0) red[tid >> 5] = v;
    __syncthreads();
    if (tid < 16) {
        v = red[tid];
        #pragma unroll
        for (int o = 8; o > 0; o >>= 1) v += __shfl_xor_sync(0xffff, v, o);
        if (tid == 0) red[0] = v;
    }
    __syncthreads();
    return red[0];
}

// ---------------- GEMM machinery (templated on NT8 = n8-tiles per block) ----------------
__device__ __forceinline__ const uint4* stage_addr(const unsigned* const* segs, int segshift,
                                                   unsigned kmask, int xstride, int k0,
                                                   int sm_m, int sm_j) {
    const unsigned* seg = segs[k0 >> segshift];
    return (const uint4*)(seg + (size_t)sm_m * xstride + (k0 & kmask) + sm_j * 4);
}

template<int NT8>
__device__ __forceinline__ void issue_w(const unsigned* __restrict__ Wf, int K16tot,
                                        int n8_0, int k16_0, unsigned dst_smem) {
    const int tid = threadIdx.x;
    #pragma unroll
    for (int f = 0; f < NT8 / 4; f++) {
        int id = f * 512 + tid;
        int kk = id / (NT8 * 32), rest = id % (NT8 * 32);
        const unsigned* src = Wf + (((size_t)(n8_0 + (rest >> 5)) * K16tot + k16_0 + kk) * 32
                                    + (rest & 31)) * 4;
        cp16(dst_smem + id * 16, src);
    }
    cp_commit();
}

template<int NT8>
__device__ __forceinline__ void prefetch_w(unsigned* dyn, const unsigned* __restrict__ Wf,
                                           int K16tot, int woff, int N, int K, int KS) {
    int ntasks = (N / (NT8 * 8)) * KS;
    int task = blockIdx.x;
    if (task >= ntasks) return;
    int nt = task / KS, ks = task - nt * KS;
    unsigned wsm = (unsigned)__cvta_generic_to_shared(dyn);
    issue_w<NT8>(Wf, K16tot, nt * NT8, woff + ((ks * (K / KS)) >> 4), wsm);
}

// single task per block (ntasks <= 148). Chunk0 W pre-issued (1 outstanding group).
template<int NT8>
__device__ void gemm_mma(unsigned* dyn, const unsigned* const* segs, int segshift, int xstride,
                         const unsigned* __restrict__ Wf, int K16tot, int woff,
                         int N, int K, int KS) {
    const int ntasks = (N / (NT8 * 8)) * KS;
    const int task = blockIdx.x;
    if (task >= ntasks) return;
    const int NTI = NT8 / 16;
    const int WB = NT8 * 512;
    unsigned* Wbuf = dyn;
    unsigned* Abuf = dyn + W_U32;
    const int Kc = K / KS;
    const int nc = Kc >> 6;
    const unsigned kmask = (1u << segshift) - 1u;
    const int tid = threadIdx.x;
    const int warp = tid >> 5, lane = tid & 31;
    const int t = lane & 3, gq = lane >> 2;
    const unsigned wsm = (unsigned)__cvta_generic_to_shared(Wbuf);

    // A staging role
    const int sm_m = tid >> 4, sm_j = tid & 15;
    const int s_row = sm_m & 15, s_g = s_row & 7, s_rh = s_row >> 3, s_mt = sm_m >> 4;
    const int s_k16 = sm_j >> 2, s_kb = (sm_j & 3) << 2;
    const int s_t0 = (s_kb >> 1) & 3;
    const int s_w = s_rh + ((s_kb >> 3) << 1);
    const int s_base = ((s_k16 * 2 + s_mt) * 32 + s_g * 4 + s_t0) * 4 + s_w;

    const int nt = task / KS, ks = task - nt * KS;
    const int n8_0 = nt * NT8;
    const int k0b = ks * Kc;
    uint4 v = *stage_addr(segs, segshift, kmask, xstride, k0b, sm_m, sm_j);

    float acc[2][NTI > 1 ? 2 : 1][4];
    #pragma unroll
    for (int mt = 0; mt < 2; mt++)
        #pragma unroll
        for (int nti = 0; nti < NTI; nti++)
            #pragma unroll
            for (int e = 0; e < 4; e++) acc[mt][nti][e] = 0.f;

    for (int c = 0; c < nc; c++) {
        const int p = c & 1;
        unsigned* abuf = Abuf + p * 2048;
        abuf[s_base]            = prmt(v.x, v.y, 0x5410);
        abuf[s_base + 4]        = prmt(v.z, v.w, 0x5410);
        abuf[1024 + s_base]     = prmt(v.x, v.y, 0x7632);
        abuf[1024 + s_base + 4] = prmt(v.z, v.w, 0x7632);
        if (c + 1 < nc) {
            issue_w<NT8>(Wf, K16tot, n8_0, woff + ((k0b + (c + 1) * 64) >> 4),
                         wsm + (p ^ 1) * (WB * 4));
            v = *stage_addr(segs, segshift, kmask, xstride, k0b + (c + 1) * 64, sm_m, sm_j);
            cp_wait<1>();
        } else {
            cp_wait<0>();
        }
        __syncthreads();
        const unsigned* wb = Wbuf + p * WB;
        #pragma unroll
        for (int kk = 0; kk < 4; kk++) {
            unsigned ah[2][4], al[2][4];
            #pragma unroll
            for (int mt = 0; mt < 2; mt++) {
                *(uint4*)ah[mt] = *(const uint4*)&abuf[((kk * 2 + mt) * 32 + lane) * 4];
                *(uint4*)al[mt] = *(const uint4*)&abuf[1024 + ((kk * 2 + mt) * 32 + lane) * 4];
            }
            #pragma unroll
            for (int nti = 0; nti < NTI; nti++) {
                const uint4 q = *(const uint4*)&wb[((kk * NT8 + warp * NTI + nti) * 32 + lane) * 4];
                #pragma unroll
                for (int mt = 0; mt < 2; mt++) {
                    mma16816(acc[mt][nti], ah[mt], q.x, q.y);
                    mma16816(acc[mt][nti], ah[mt], q.z, q.w);
                    mma16816(acc[mt][nti], al[mt], q.x, q.y);
                }
            }
        }
        __syncthreads();
    }
    float* dst = g_part + (size_t)ks * BB * N;
    const int n0w = nt * (NT8 * 8) + warp * (NTI * 8);
    #pragma unroll
    for (int mt = 0; mt < 2; mt++) {
        int m = mt * 16 + gq;
        #pragma unroll
        for (int nti = 0; nti < NTI; nti++) {
            int n = n0w + nti * 8 + t * 2;
            *(float2*)&dst[(size_t)m * N + n]       = make_float2(acc[mt][nti][0], acc[mt][nti][1]);
            *(float2*)&dst[(size_t)(m + 8) * N + n] = make_float2(acc[mt][nti][2], acc[mt][nti][3]);
        }
    }
}

// ---------------- LN (+ReLU), float4 path ----------------
__device__ void ln_phase(SmemL& sm, const float* __restrict__ pre, const float* __restrict__ bias,
                         const float* __restrict__ gam, const float* __restrict__ bet,
                         int N, int KS, int mode, int i, float* __restrict__ out_states) {
    int b = blockIdx.x;
    if (b >= BB) return;
    int tid = threadIdx.x;
    const int N4 = N >> 2;
    float s = 0.f, ss = 0.f;
    for (int j4 = tid; j4 < N4; j4 += 512) {
        float4 v = pre ? ((const float4*)pre)[b * N4 + j4] : ((const float4*)bias)[j4];
        for (int ks = 0; ks < KS; ks++) {
            float4 p = ((const float4*)g_part)[((size_t)ks * BB + b) * N4 + j4];
            v.x += p.x; v.y += p.y; v.z += p.z; v.w += p.w;
        }
        ((float4*)sm.buf)[j4] = v;
        s += v.x + v.y + v.z + v.w;
        ss += v.x * v.x + v.y * v.y + v.z * v.z + v.w * v.w;
    }
    float mu = block_reduce(s, sm.red) / (float)N;
    float var = block_reduce(ss, sm.red) / (float)N - mu * mu;
    float rs = rsqrtf(var + 1e-5f);
    for (int j4 = tid; j4 < N4; j4 += 512) {
        float4 v = ((const float4*)sm.buf)[j4];
        float4 gm = ((const float4*)gam)[j4];
        float4 bt = ((const float4*)bet)[j4];
        float4 y;
        y.x = fmaxf((v.x - mu) * rs * gm.x + bt.x, 0.f);
        y.y = fmaxf((v.y - mu) * rs * gm.y + bt.y, 0.f);
        y.z = fmaxf((v.z - mu) * rs * gm.z + bt.z, 0.f);
        y.w = fmaxf((v.w - mu) * rs * gm.w + bt.w, 0.f);
        if (mode == 1) {
            uint4 p = make_uint4(packsplit(y.x), packsplit(y.y), packsplit(y.z), packsplit(y.w));
            ((uint4*)g_interp)[b * 1024 + j4] = p;
        } else {
            if (j4 < 256) {
                ((float4*)(g_keys + ((size_t)(i + 1) * BB + b) * NHID))[j4] = y;
            } else if (j4 < 512) {
                ((float4*)(g_vals + ((size_t)(i + 1) * BB + b) * NHID))[j4 - 256] = y;
            } else {
                int jj4 = j4 - 512;
                uint4 p = make_uint4(packsplit(y.x), packsplit(y.y), packsplit(y.z), packsplit(y.w));
                ((uint4*)g_hidp)[b * 256 + jj4] = p;
                ((uint4*)g_spack)[((size_t)i * BB + b) * 256 + jj4] = p;
                ((float4*)(out_states + ((size_t)(i + 1) * BB + b) * NHID))[jj4] = y;
            }
        }
    }
}

// ---------------- fused LN(q) + attention ----------------
__device__ void ln_attn_phase(SmemL& sm, const float* __restrict__ pre,
                              const float* __restrict__ gam, const float* __restrict__ bet, int i) {
    int b = blockIdx.x;
    if (b >= BB) return;
    int tid = threadIdx.x;
    float s = 0.f, ss = 0.f;
    if (tid < 256) {
        int j4 = tid;
        float4 v = ((const float4*)pre)[b * 256 + j4];
        #pragma unroll
        for (int ks = 0; ks < 16; ks++) {
            float4 p = ((const float4*)g_part)[((size_t)ks * BB + b) * 256 + j4];
            v.x += p.x; v.y += p.y; v.z += p.z; v.w += p.w;
        }
        ((float4*)sm.buf)[j4] = v;
        s = v.x + v.y + v.z + v.w;
        ss = v.x * v.x + v.y * v.y + v.z * v.z + v.w * v.w;
    }
    float mu = block_reduce(s, sm.red) / 1024.f;
    float var = block_reduce(ss, sm.red) / 1024.f - mu * mu;
    float rs = rsqrtf(var + 1e-5f);
    if (tid < 256) {
        int j4 = tid;
        float4 v = ((const float4*)sm.buf)[j4];
        float4 gm = ((const float4*)gam)[j4];
        float4 bt = ((const float4*)bet)[j4];
        float4 y;
        y.x = fmaxf((v.x - mu) * rs * gm.x + bt.x, 0.f);
        y.y = fmaxf((v.y - mu) * rs * gm.y + bt.y, 0.f);
        y.z = fmaxf((v.z - mu) * rs * gm.z + bt.z, 0.f);
        y.w = fmaxf((v.w - mu) * rs * gm.w + bt.w, 0.f);
        ((float4*)sm.qs)[j4] = y;
        uint4 p = make_uint4(packsplit(y.x), packsplit(y.y), packsplit(y.z), packsplit(y.w));
        ((uint4*)g_qp)[b * 256 + j4] = p;
    }
    __syncthreads();

    int len = i + 1;
    int hd = tid >> 5, lane = tid & 31;
    {
        float sv[4];
        float mx = -1e30f;
        #pragma unroll
        for (int r = 0; r < 4; r++) {
            int c = lane + 32 * r;
            float d = -1e30f;
            if (c < len) {
                const float* kp = g_keys + ((size_t)c * BB + b) * NHID + hd * HDIM;
                float a2 = 0.f;
                #pragma unroll
                for (int h = 0; h < HDIM; h += 4) {
                    float4 kv = *(const float4*)&kp[h];
                    a2 += kv.x * sm.qs[hd * HDIM + h]     + kv.y * sm.qs[hd * HDIM + h + 1]
                        + kv.z * sm.qs[hd * HDIM + h + 2] + kv.w * sm.qs[hd * HDIM + h + 3];
                }
                d = a2 * 0.125f;
            }
            sv[r] = d;
            mx = fmaxf(mx, d);
        }
        #pragma unroll
        for (int o = 16; o > 0; o >>= 1) mx = fmaxf(mx, __shfl_xor_sync(~0u, mx, o));
        float sum = 0.f;
        #pragma unroll
        for (int r = 0; r < 4; r++) {
            int c = lane + 32 * r;
            float e = (c < len) ? __expf(sv[r] - mx) : 0.f;
            sv[r] = e; sum += e;
        }
        #pragma unroll
        for (int o = 16; o > 0; o >>= 1) sum += __shfl_xor_sync(~0u, sum, o);
        float inv = 1.f / sum;
        #pragma unroll
        for (int r = 0; r < 4; r++) {
            int c = lane + 32 * r;
            if (c < len) sm.sc[hd][c] = sv[r] * inv;
        }
    }
    __syncthreads();

    for (int idx = tid; idx < 1024; idx += 512) {
        int h2 = idx >> 6, h = idx & 63;
        float a = 0.f;
        const float* vp = g_vals + b * NHID + h2 * HDIM + h;
        #pragma unroll 4
        for (int c = 0; c < len; c++) a += sm.sc[h2][c] * vp[(size_t)c * BB * NHID];
        g_attnp[b * 1024 + idx] = packsplit(a);
    }
}

// ---------------- persistent sequence kernel ----------------
__global__ void __launch_bounds__(512, 1) k_seq(
    const float* __restrict__ qn_g,  const float* __restrict__ qn_b,
    const float* __restrict__ intn_g,const float* __restrict__ intn_b,
    const float* __restrict__ fin_b, const float* __restrict__ fn_g,
    const float* __restrict__ fn_b,  float* __restrict__ out_states)
{
    extern __shared__ __align__(16) unsigned dyn[];
    SmemL& sml = *reinterpret_cast<SmemL*>(dyn + W_U32 + A_U32);

    prefetch_w<16>(dyn, g_qwp, 128, 64, 1024, 1024, 16);

    for (int i = 0; i < SS; i++) {
        {   // GEMM1: hidden @ q_w[:,1024:]^T  (NT8=16, N=1024, K=1024, KS=16 -> 128 tasks)
            const unsigned* segs[4] = { g_hidp, g_hidp, g_hidp, g_hidp };
            gemm_mma<16>(dyn, segs, 10, 1024, g_qwp, 128, 64, 1024, 1024, 16);
        }
        prefetch_w<32>(dyn, g_intwp, 256, 64, 4096, 3072, 8);
        gridbar();
        ln_attn_phase(sml, g_p1 + (size_t)i * BB * 1024, qn_g, qn_b, i);
        gridbar();
        {   // GEMM2: [q|attn|hidden] @ int_w[:,1024:]^T (NT8=32, N=4096, K=3072, KS=8 -> 128 tasks)
            const unsigned* segs[4] = { g_qp, g_attnp, g_hidp, g_hidp };
            gemm_mma<32>(dyn, segs, 10, 1024, g_intwp, 256, 64, 4096, 3072, 8);
        }
        prefetch_w<32>(dyn, g_finwp, 256, 0, 3072, 4096, 8);
        gridbar();
        ln_phase(sml, g_p2 + (size_t)i * BB * 4096, 0, intn_g, intn_b, 4096, 8, 1, i, out_states);
        gridbar();
        {   // GEMM3: inter @ fin_w^T (NT8=32, N=3072, K=4096, KS=8 -> 96 tasks)
            const unsigned* segs[4] = { g_interp, g_interp, g_interp, g_interp };
            gemm_mma<32>(dyn, segs, 12, 4096, g_finwp, 256, 0, 3072, 4096, 8);
        }
        prefetch_w<16>(dyn, g_qwp, 128, 64, 1024, 1024, 16);
        gridbar();
        ln_phase(sml, 0, fin_b, fn_g, fn_b, 3072, 8, 2, i, out_states);
        gridbar();
    }
}

// ---------------- weight convert (all four in one kernel) ----------------
__device__ __forceinline__ void convert_range(const float* __restrict__ w,
                                              unsigned* __restrict__ wf, int total, int kshift) {
    const int K = 1 << kshift;
    const int halfK = K >> 1;
    const int pairs = total >> 1;
    for (int i = blockIdx.x * 256 + threadIdx.x; i < pairs; i += gridDim.x * 256) {
        int kp = i & (halfK - 1);
        int n  = i >> (kshift - 1);
        int k  = kp << 1;
        unsigned p0 = packsplit(w[((size_t)n << kshift) + k]);
        unsigned p1 = packsplit(w[((size_t)n << kshift) + k + 1]);
        unsigned bh = prmt(p0, p1, 0x5410);
        unsigned bl = prmt(p0, p1, 0x7632);
        int n8 = n >> 3, g = n & 7;
        int k16 = k >> 4, kr = k & 15;
        int j = kr >> 1, t = j & 3, half = j >> 2;
        size_t base = (((size_t)n8 * (K >> 4) + k16) * 32 + g * 4 + t) * 4;
        wf[base + half]     = bh;
        wf[base + 2 + half] = bl;
    }
}
__global__ void k_convert_all(const float* __restrict__ q_w, const float* __restrict__ int_w,
                              const float* __restrict__ fin_w, const float* __restrict__ dec_w) {
    convert_range(q_w,   g_qwp,   1024 * 2048, 11);
    convert_range(int_w, g_intwp, 4096 * 4096, 12);
    convert_range(fin_w, g_finwp, 3072 * 4096, 12);
    convert_range(dec_w, g_decwp, VV * 1024,   10);
}

// ---------------- embedding gather (packed) ----------------
__global__ void k_embed(const int* __restrict__ obs, const float* __restrict__ enc_w) {
    int sb = blockIdx.x;
    int tok = obs[sb];
    const float4* src = (const float4*)(enc_w + (size_t)tok * 1024);
    float4 v = src[threadIdx.x];
    uint4 p = make_uint4(packsplit(v.x), packsplit(v.y), packsplit(v.z), packsplit(v.w));
    ((uint4*)(g_embp + (size_t)sb * 1024))[threadIdx.x] = p;
}

// ---------------- init ----------------
__global__ void k_init(const float* __restrict__ hidden_init,
                       const float* __restrict__ kci,
                       const float* __restrict__ vci,
                       float* __restrict__ out_states) {
    if (blockIdx.x == 0 && threadIdx.x == 0) { g_cnt = 0; g_gen = 0; }
    int idx = blockIdx.x * 256 + threadIdx.x;
    float4 h = ((const float4*)hidden_init)[idx];
    ((float4*)out_states)[idx] = h;
    ((float4*)g_keys)[idx] = ((const float4*)kci)[idx];
    ((float4*)g_vals)[idx] = ((const float4*)vci)[idx];
    uint4 p = make_uint4(packsplit(h.x), packsplit(h.y), packsplit(h.z), packsplit(h.w));
    ((uint4*)g_hidp)[idx] = p;
}

// ---------------- big-M GEMM: out[4096][ld] = A[4096 x 1024] @ Wf^T + bias ----------------
__global__ void __launch_bounds__(512, 1) k_bigmm(const unsigned* __restrict__ A,
                                                  const unsigned* __restrict__ Wf,
                                                  int K16tot, int woff,
                                                  const float* __restrict__ bias,
                                                  float* __restrict__ out, int ldout) {
    const int m0 = blockIdx.x * 128;
    const int n0 = blockIdx.y * 256;
    const int warp = threadIdx.x >> 5, lane = threadIdx.x & 31;
    const int g = lane >> 2, t = lane & 3;
    const int mb = m0 + (warp & 3) * 32;
    const int nb = n0 + (warp >> 2) * 64;
    const int n8b = nb >> 3;

    float acc[2][8][4];
    #pragma unroll
    for (int mt = 0; mt < 2; mt++)
        #pragma unroll
        for (int ni = 0; ni < 8; ni++)
            #pragma unroll
            for (int e = 0; e < 4; e++) acc[mt][ni][e] = 0.f;

    for (int k0 = 0; k0 < 1024; k0 += 16) {
        unsigned ahi[2][4], alo[2][4];
        #pragma unroll
        for (int mt = 0; mt < 2; mt++) {
            const unsigned* x0 = A + (size_t)(mb + mt * 16 + g) * 1024 + k0 + t * 2;
            const unsigned* x8 = x0 + 8 * 1024;
            uint2 p0 = *(const uint2*)x0;
            uint2 p1 = *(const uint2*)x8;
            uint2 p2 = *(const uint2*)(x0 + 8);
            uint2 p3 = *(const uint2*)(x8 + 8);
            ahi[mt][0] = prmt(p0.x, p0.y, 0x5410); alo[mt][0] = prmt(p0.x, p0.y, 0x7632);
            ahi[mt][1] = prmt(p1.x, p1.y, 0x5410); alo[mt][1] = prmt(p1.x, p1.y, 0x7632);
            ahi[mt][2] = prmt(p2.x, p2.y, 0x5410); alo[mt][2] = prmt(p2.x, p2.y, 0x7632);
            ahi[mt][3] = prmt(p3.x, p3.y, 0x5410); alo[mt][3] = prmt(p3.x, p3.y, 0x7632);
        }
        #pragma unroll
        for (int ni = 0; ni < 8; ni++) {
            const uint4 q = *(const uint4*)(Wf + (((size_t)(n8b + ni) * K16tot + woff + (k0 >> 4)) * 32 + lane) * 4);
            #pragma unroll
            for (int mt = 0; mt < 2; mt++) {
                mma16816(acc[mt][ni], ahi[mt], q.x, q.y);
                mma16816(acc[mt][ni], ahi[mt], q.z, q.w);
                mma16816(acc[mt][ni], alo[mt], q.x, q.y);
            }
        }
    }
    #pragma unroll
    for (int mt = 0; mt < 2; mt++) {
        int m = mb + mt * 16 + g;
        #pragma unroll
        for (int ni = 0; ni < 8; ni++) {
            int n = nb + ni * 8 + t * 2;
            float bx = bias[n], by = bias[n + 1];
            *(float2*)&out[(size_t)m * ldout + n]       = make_float2(acc[mt][ni][0] + bx, acc[mt][ni][1] + by);
            *(float2*)&out[(size_t)(m + 8) * ldout + n] = make_float2(acc[mt][ni][2] + bx, acc[mt][ni][3] + by);
        }
    }
}

// ---------------- launch ----------------
extern "C" void kernel_launch(void* const* d_in, const int* in_sizes, int n_in,
                              void* d_out, int out_size) {
    const int*   obs         = (const int*)d_in[0];
    const float* hidden_init = (const float*)d_in[1];
    const float* kci         = (const float*)d_in[2];
    const float* vci         = (const float*)d_in[3];
    const float* enc_w       = (const float*)d_in[4];
    const float* q_w         = (const float*)d_in[5];
    const float* q_b         = (const float*)d_in[6];
    const float* qn_g        = (const float*)d_in[7];
    const float* qn_b        = (const float*)d_in[8];
    const float* int_w       = (const float*)d_in[9];
    const float* int_b       = (const float*)d_in[10];
    const float* intn_g      = (const float*)d_in[11];
    const float* intn_b      = (const float*)d_in[12];
    const float* fin_w       = (const float*)d_in[13];
    const float* fin_b       = (const float*)d_in[14];
    const float* fn_g        = (const float*)d_in[15];
    const float* fn_b        = (const float*)d_in[16];
    const float* dec_w       = (const float*)d_in[17];
    const float* dec_b       = (const float*)d_in[18];

    float* out        = (float*)d_out;
    float* out_states = out + (size_t)SS * BB * VV;

    unsigned* qwp;  cudaGetSymbolAddress((void**)&qwp,  g_qwp);
    unsigned* iwp;  cudaGetSymbolAddress((void**)&iwp,  g_intwp);
    unsigned* dwp;  cudaGetSymbolAddress((void**)&dwp,  g_decwp);
    unsigned* emb;  cudaGetSymbolAddress((void**)&emb,  g_embp);
    unsigned* spk;  cudaGetSymbolAddress((void**)&spk,  g_spack);
    float* p1;      cudaGetSymbolAddress((void**)&p1,   g_p1);
    float* p2;      cudaGetSymbolAddress((void**)&p2,   g_p2);

    const int smem_bytes = (W_U32 + A_U32) * 4 + (int)sizeof(SmemL);
    static int smem_set = 0;
    if (!smem_set) {
        cudaFuncSetAttribute(k_seq, cudaFuncAttributeMaxDynamicSharedMemorySize, smem_bytes);
        smem_set = 1;
    }

    k_convert_all<<<4096, 256>>>(q_w, int_w, fin_w, dec_w);
    k_embed<<<SS * BB, 256>>>(obs, enc_w);
    k_init<<<32, 256>>>(hidden_init, kci, vci, out_states);

    // precompute embedding contributions (bias folded)
    k_bigmm<<<dim3(32, 4),  512>>>(emb, qwp, 128, 0, q_b,   p1, 1024);
    k_bigmm<<<dim3(32, 16), 512>>>(emb, iwp, 256, 0, int_b, p2, 4096);

    k_seq<<<NBLK, 512, smem_bytes>>>(qn_g, qn_b, intn_g, intn_b,
                                     fin_b, fn_g, fn_b, out_states);

    // decoder
    k_bigmm<<<dim3(32, VV / 256), 512>>>(spk, dwp, 64, 0, dec_b, out, VV);
}

// round 11
// speedup vs baseline: 1.1718x; 1.0151x over previous
#include <cuda_runtime.h>
#include <cuda_bf16.h>
#include <math.h>

#define SS   128
#define BB   32
#define NHID 1024
#define NH   16
#define HDIM 64
#define VV   32000
#define NBLK 148

#define W_U32 32768     // 2 x 16384 u32 = 128 KB W ping-pong (max, NT8=32)
#define A_U32 4096      // 2 x 2048 u32  = 16 KB  A ping-pong

// ---------------- scratch (device globals; no allocation) ----------------
__device__ float g_keys[(SS + 1) * BB * NHID];
__device__ float g_vals[(SS + 1) * BB * NHID];
__device__ float g_part[16 * BB * 4096];
__device__ float g_p1[SS * BB * 1024];
__device__ float g_p2[SS * BB * 4096];
__device__ unsigned g_gmc[3];    // GEMM phase completions (monotonic, 148/step each)
__device__ unsigned g_lnc[3];    // LN phase completions   (monotonic, 32/step each)

// fragment-ordered, pre-split weights: per (n8,k16,lane) uint4 = (b0h,b1h,b0l,b1l)
__device__ __align__(16) unsigned g_qwp  [1024 * 2048];
__device__ __align__(16) unsigned g_intwp[4096 * 4096];
__device__ __align__(16) unsigned g_finwp[3072 * 4096];
__device__ __align__(16) unsigned g_decwp[VV * 1024];
// row-major packed (hi,lo) activations
__device__ __align__(16) unsigned g_embp [SS * BB * 1024];
__device__ __align__(16) unsigned g_hidp [BB * 1024];
__device__ __align__(16) unsigned g_qp   [BB * 1024];
__device__ __align__(16) unsigned g_attnp[BB * 1024];
__device__ __align__(16) unsigned g_interp[BB * 4096];
__device__ __align__(16) unsigned g_spack[SS * BB * 1024];

// ---------------- helpers ----------------
__device__ __forceinline__ unsigned packsplit(float x) {
    __nv_bfloat16 h = __float2bfloat16(x);
    __nv_bfloat16 l = __float2bfloat16(x - __bfloat162float(h));
    return (unsigned)__bfloat16_as_ushort(h) | ((unsigned)__bfloat16_as_ushort(l) << 16);
}
__device__ __forceinline__ unsigned prmt(unsigned a, unsigned b, unsigned s) {
    unsigned d; asm("prmt.b32 %0,%1,%2,%3;" : "=r"(d) : "r"(a), "r"(b), "r"(s)); return d;
}
__device__ __forceinline__ void mma16816(float* c, const unsigned* a, unsigned b0, unsigned b1) {
    asm volatile(
        "mma.sync.aligned.m16n8k16.row.col.f32.bf16.bf16.f32 "
        "{%0,%1,%2,%3}, {%4,%5,%6,%7}, {%8,%9}, {%0,%1,%2,%3};"
        : "+f"(c[0]), "+f"(c[1]), "+f"(c[2]), "+f"(c[3])
        : "r"(a[0]), "r"(a[1]), "r"(a[2]), "r"(a[3]), "r"(b0), "r"(b1));
}
__device__ __forceinline__ void cp16(unsigned dst, const void* src) {
    asm volatile("cp.async.cg.shared.global [%0], [%1], 16;" :: "r"(dst), "l"(src));
}
__device__ __forceinline__ void cp_commit() { asm volatile("cp.async.commit_group;"); }
template<int N_> __device__ __forceinline__ void cp_wait() {
    asm volatile("cp.async.wait_group %0;" :: "n"(N_));
}

// ---------------- event counters ----------------
__device__ __forceinline__ void signal(unsigned* c) {
    __syncthreads();                       // all block writes done
    if (threadIdx.x == 0) { __threadfence(); atomicAdd(c, 1u); }
}
__device__ __forceinline__ void wait_ge(volatile unsigned* c, unsigned tgt) {
    if (threadIdx.x == 0) {
        while (*c < tgt) { __nanosleep(64); }
        __threadfence();                   // invalidate stale L1
    }
    __syncthreads();
}

struct SmemL { float buf[4096]; float red[32]; float qs[1024]; float sc[16][132]; };

__device__ __forceinline__ float block_reduce(float v, float* red) {
    __syncthreads();
    int tid = threadIdx.x;
    #pragma unroll
    for (int o = 16; o > 0; o >>= 1) v += __shfl_xor_sync(~0u, v, o);
    if ((tid & 31) == 0) red[tid >> 5] = v;
    __syncthreads();
    if (tid < 16) {
        v = red[tid];
        #pragma unroll
        for (int o = 8; o > 0; o >>= 1) v += __shfl_xor_sync(0xffff, v, o);
        if (tid == 0) red[0] = v;
    }
    __syncthreads();
    return red[0];
}

// ---------------- GEMM machinery (templated on NT8 = n8-tiles per block) ----------------
__device__ __forceinline__ const uint4* stage_addr(const unsigned* const* segs, int segshift,
                                                   unsigned kmask, int xstride, int k0,
                                                   int sm_m, int sm_j) {
    const unsigned* seg = segs[k0 >> segshift];
    return (const uint4*)(seg + (size_t)sm_m * xstride + (k0 & kmask) + sm_j * 4);
}

template<int NT8>
__device__ __forceinline__ void issue_w(const unsigned* __restrict__ Wf, int K16tot,
                                        int n8_0, int k16_0, unsigned dst_smem) {
    const int tid = threadIdx.x;
    #pragma unroll
    for (int f = 0; f < NT8 / 4; f++) {
        int id = f * 512 + tid;
        int kk = id / (NT8 * 32), rest = id % (NT8 * 32);
        const unsigned* src = Wf + (((size_t)(n8_0 + (rest >> 5)) * K16tot + k16_0 + kk) * 32
                                    + (rest & 31)) * 4;
        cp16(dst_smem + id * 16, src);
    }
    cp_commit();
}

// issue chunk0 (and chunk1 if present) before the LN wait — overlaps LN with W stream
template<int NT8>
__device__ __forceinline__ void prefetch2(unsigned* dyn, const unsigned* __restrict__ Wf,
                                          int K16tot, int woff, int N, int K, int KS) {
    int ntasks = (N / (NT8 * 8)) * KS;
    int task = blockIdx.x;
    if (task >= ntasks) return;
    int nt = task / KS, ks = task - nt * KS;
    int Kc = K / KS, nc = Kc >> 6;
    unsigned wsm = (unsigned)__cvta_generic_to_shared(dyn);
    int k16 = woff + ((ks * Kc) >> 4);
    issue_w<NT8>(Wf, K16tot, nt * NT8, k16, wsm);
    if (nc > 1) issue_w<NT8>(Wf, K16tot, nt * NT8, k16 + 4, wsm + NT8 * 2048);
}

// single task per block. Entry: chunk0 (+chunk1 if nc>1) groups outstanding.
template<int NT8>
__device__ void gemm_mma(unsigned* dyn, const unsigned* const* segs, int segshift, int xstride,
                         const unsigned* __restrict__ Wf, int K16tot, int woff,
                         int N, int K, int KS) {
    const int ntasks = (N / (NT8 * 8)) * KS;
    const int task = blockIdx.x;
    if (task >= ntasks) return;
    const int NTI = NT8 / 16;
    const int WB = NT8 * 512;
    unsigned* Wbuf = dyn;
    unsigned* Abuf = dyn + W_U32;
    const int Kc = K / KS;
    const int nc = Kc >> 6;
    const unsigned kmask = (1u << segshift) - 1u;
    const int tid = threadIdx.x;
    const int warp = tid >> 5, lane = tid & 31;
    const int t = lane & 3, gq = lane >> 2;
    const unsigned wsm = (unsigned)__cvta_generic_to_shared(Wbuf);

    // A staging role
    const int sm_m = tid >> 4, sm_j = tid & 15;
    const int s_row = sm_m & 15, s_g = s_row & 7, s_rh = s_row >> 3, s_mt = sm_m >> 4;
    const int s_k16 = sm_j >> 2, s_kb = (sm_j & 3) << 2;
    const int s_t0 = (s_kb >> 1) & 3;
    const int s_w = s_rh + ((s_kb >> 3) << 1);
    const int s_base = ((s_k16 * 2 + s_mt) * 32 + s_g * 4 + s_t0) * 4 + s_w;

    const int nt = task / KS, ks = task - nt * KS;
    const int n8_0 = nt * NT8;
    const int k0b = ks * Kc;
    uint4 v = *stage_addr(segs, segshift, kmask, xstride, k0b, sm_m, sm_j);

    float acc[2][NTI > 1 ? 2 : 1][4];
    #pragma unroll
    for (int mt = 0; mt < 2; mt++)
        #pragma unroll
        for (int nti = 0; nti < NTI; nti++)
            #pragma unroll
            for (int e = 0; e < 4; e++) acc[mt][nti][e] = 0.f;

    for (int c = 0; c < nc; c++) {
        const int p = c & 1;
        unsigned* abuf = Abuf + p * 2048;
        abuf[s_base]            = prmt(v.x, v.y, 0x5410);
        abuf[s_base + 4]        = prmt(v.z, v.w, 0x5410);
        abuf[1024 + s_base]     = prmt(v.x, v.y, 0x7632);
        abuf[1024 + s_base + 4] = prmt(v.z, v.w, 0x7632);
        if (c + 1 < nc) {
            v = *stage_addr(segs, segshift, kmask, xstride, k0b + (c + 1) * 64, sm_m, sm_j);
            cp_wait<1>();       // chunk c arrived, chunk c+1 in flight
        } else {
            cp_wait<0>();
        }
        __syncthreads();
        const unsigned* wb = Wbuf + p * WB;
        #pragma unroll
        for (int kk = 0; kk < 4; kk++) {
            unsigned ah[2][4], al[2][4];
            #pragma unroll
            for (int mt = 0; mt < 2; mt++) {
                *(uint4*)ah[mt] = *(const uint4*)&abuf[((kk * 2 + mt) * 32 + lane) * 4];
                *(uint4*)al[mt] = *(const uint4*)&abuf[1024 + ((kk * 2 + mt) * 32 + lane) * 4];
            }
            #pragma unroll
            for (int nti = 0; nti < NTI; nti++) {
                const uint4 q = *(const uint4*)&wb[((kk * NT8 + warp * NTI + nti) * 32 + lane) * 4];
                #pragma unroll
                for (int mt = 0; mt < 2; mt++) {
                    mma16816(acc[mt][nti], ah[mt], q.x, q.y);
                    mma16816(acc[mt][nti], ah[mt], q.z, q.w);
                    mma16816(acc[mt][nti], al[mt], q.x, q.y);
                }
            }
        }
        __syncthreads();
        if (c + 2 < nc)         // refill the buffer we just consumed
            issue_w<NT8>(Wf, K16tot, n8_0, woff + (k0b >> 4) + (c + 2) * 4,
                         wsm + p * (WB * 4));
    }
    float* dst = g_part + (size_t)ks * BB * N;
    const int n0w = nt * (NT8 * 8) + warp * (NTI * 8);
    #pragma unroll
    for (int mt = 0; mt < 2; mt++) {
        int m = mt * 16 + gq;
        #pragma unroll
        for (int nti = 0; nti < NTI; nti++) {
            int n = n0w + nti * 8 + t * 2;
            *(float2*)&dst[(size_t)m * N + n]       = make_float2(acc[mt][nti][0], acc[mt][nti][1]);
            *(float2*)&dst[(size_t)(m + 8) * N + n] = make_float2(acc[mt][nti][2], acc[mt][nti][3]);
        }
    }
}

// ---------------- LN (+ReLU), float4 path ----------------
__device__ void ln_phase(SmemL& sm, const float* __restrict__ pre, const float* __restrict__ bias,
                         const float* __restrict__ gam, const float* __restrict__ bet,
                         int N, int KS, int mode, int i, float* __restrict__ out_states) {
    int b = blockIdx.x;
    if (b >= BB) return;
    int tid = threadIdx.x;
    const int N4 = N >> 2;
    float s = 0.f, ss = 0.f;
    for (int j4 = tid; j4 < N4; j4 += 512) {
        float4 v = pre ? ((const float4*)pre)[b * N4 + j4] : ((const float4*)bias)[j4];
        for (int ks = 0; ks < KS; ks++) {
            float4 p = ((const float4*)g_part)[((size_t)ks * BB + b) * N4 + j4];
            v.x += p.x; v.y += p.y; v.z += p.z; v.w += p.w;
        }
        ((float4*)sm.buf)[j4] = v;
        s += v.x + v.y + v.z + v.w;
        ss += v.x * v.x + v.y * v.y + v.z * v.z + v.w * v.w;
    }
    float mu = block_reduce(s, sm.red) / (float)N;
    float var = block_reduce(ss, sm.red) / (float)N - mu * mu;
    float rs = rsqrtf(var + 1e-5f);
    for (int j4 = tid; j4 < N4; j4 += 512) {
        float4 v = ((const float4*)sm.buf)[j4];
        float4 gm = ((const float4*)gam)[j4];
        float4 bt = ((const float4*)bet)[j4];
        float4 y;
        y.x = fmaxf((v.x - mu) * rs * gm.x + bt.x, 0.f);
        y.y = fmaxf((v.y - mu) * rs * gm.y + bt.y, 0.f);
        y.z = fmaxf((v.z - mu) * rs * gm.z + bt.z, 0.f);
        y.w = fmaxf((v.w - mu) * rs * gm.w + bt.w, 0.f);
        if (mode == 1) {
            uint4 p = make_uint4(packsplit(y.x), packsplit(y.y), packsplit(y.z), packsplit(y.w));
            ((uint4*)g_interp)[b * 1024 + j4] = p;
        } else {
            if (j4 < 256) {
                ((float4*)(g_keys + ((size_t)(i + 1) * BB + b) * NHID))[j4] = y;
            } else if (j4 < 512) {
                ((float4*)(g_vals + ((size_t)(i + 1) * BB + b) * NHID))[j4 - 256] = y;
            } else {
                int jj4 = j4 - 512;
                uint4 p = make_uint4(packsplit(y.x), packsplit(y.y), packsplit(y.z), packsplit(y.w));
                ((uint4*)g_hidp)[b * 256 + jj4] = p;
                ((uint4*)g_spack)[((size_t)i * BB + b) * 256 + jj4] = p;
                ((float4*)(out_states + ((size_t)(i + 1) * BB + b) * NHID))[jj4] = y;
            }
        }
    }
}

// ---------------- fused LN(q) + attention ----------------
__device__ void ln_attn_phase(SmemL& sm, const float* __restrict__ pre,
                              const float* __restrict__ gam, const float* __restrict__ bet, int i) {
    int b = blockIdx.x;
    if (b >= BB) return;
    int tid = threadIdx.x;
    float s = 0.f, ss = 0.f;
    if (tid < 256) {
        int j4 = tid;
        float4 v = ((const float4*)pre)[b * 256 + j4];
        #pragma unroll
        for (int ks = 0; ks < 16; ks++) {
            float4 p = ((const float4*)g_part)[((size_t)ks * BB + b) * 256 + j4];
            v.x += p.x; v.y += p.y; v.z += p.z; v.w += p.w;
        }
        ((float4*)sm.buf)[j4] = v;
        s = v.x + v.y + v.z + v.w;
        ss = v.x * v.x + v.y * v.y + v.z * v.z + v.w * v.w;
    }
    float mu = block_reduce(s, sm.red) / 1024.f;
    float var = block_reduce(ss, sm.red) / 1024.f - mu * mu;
    float rs = rsqrtf(var + 1e-5f);
    if (tid < 256) {
        int j4 = tid;
        float4 v = ((const float4*)sm.buf)[j4];
        float4 gm = ((const float4*)gam)[j4];
        float4 bt = ((const float4*)bet)[j4];
        float4 y;
        y.x = fmaxf((v.x - mu) * rs * gm.x + bt.x, 0.f);
        y.y = fmaxf((v.y - mu) * rs * gm.y + bt.y, 0.f);
        y.z = fmaxf((v.z - mu) * rs * gm.z + bt.z, 0.f);
        y.w = fmaxf((v.w - mu) * rs * gm.w + bt.w, 0.f);
        ((float4*)sm.qs)[j4] = y;
        uint4 p = make_uint4(packsplit(y.x), packsplit(y.y), packsplit(y.z), packsplit(y.w));
        ((uint4*)g_qp)[b * 256 + j4] = p;
    }
    __syncthreads();

    int len = i + 1;
    int hd = tid >> 5, lane = tid & 31;
    {
        float sv[4];
        float mx = -1e30f;
        #pragma unroll
        for (int r = 0; r < 4; r++) {
            int c = lane + 32 * r;
            float d = -1e30f;
            if (c < len) {
                const float* kp = g_keys + ((size_t)c * BB + b) * NHID + hd * HDIM;
                float a2 = 0.f;
                #pragma unroll
                for (int h = 0; h < HDIM; h += 4) {
                    float4 kv = *(const float4*)&kp[h];
                    a2 += kv.x * sm.qs[hd * HDIM + h]     + kv.y * sm.qs[hd * HDIM + h + 1]
                        + kv.z * sm.qs[hd * HDIM + h + 2] + kv.w * sm.qs[hd * HDIM + h + 3];
                }
                d = a2 * 0.125f;
            }
            sv[r] = d;
            mx = fmaxf(mx, d);
        }
        #pragma unroll
        for (int o = 16; o > 0; o >>= 1) mx = fmaxf(mx, __shfl_xor_sync(~0u, mx, o));
        float sum = 0.f;
        #pragma unroll
        for (int r = 0; r < 4; r++) {
            int c = lane + 32 * r;
            float e = (c < len) ? __expf(sv[r] - mx) : 0.f;
            sv[r] = e; sum += e;
        }
        #pragma unroll
        for (int o = 16; o > 0; o >>= 1) sum += __shfl_xor_sync(~0u, sum, o);
        float inv = 1.f / sum;
        #pragma unroll
        for (int r = 0; r < 4; r++) {
            int c = lane + 32 * r;
            if (c < len) sm.sc[hd][c] = sv[r] * inv;
        }
    }
    __syncthreads();

    for (int idx = tid; idx < 1024; idx += 512) {
        int h2 = idx >> 6, h = idx & 63;
        float a = 0.f;
        const float* vp = g_vals + b * NHID + h2 * HDIM + h;
        #pragma unroll 4
        for (int c = 0; c < len; c++) a += sm.sc[h2][c] * vp[(size_t)c * BB * NHID];
        g_attnp[b * 1024 + idx] = packsplit(a);
    }
}

// ---------------- persistent sequence kernel (event-count synchronized) ----------------
__global__ void __launch_bounds__(512, 1) k_seq(
    const float* __restrict__ qn_g,  const float* __restrict__ qn_b,
    const float* __restrict__ intn_g,const float* __restrict__ intn_b,
    const float* __restrict__ fin_b, const float* __restrict__ fn_g,
    const float* __restrict__ fn_b,  float* __restrict__ out_states)
{
    extern __shared__ __align__(16) unsigned dyn[];
    SmemL& sml = *reinterpret_cast<SmemL*>(dyn + W_U32 + A_U32);
    const bool is_ln = (blockIdx.x < BB);

    prefetch2<16>(dyn, g_qwp, 128, 64, 1024, 1024, 16);

    for (int i = 0; i < SS; i++) {
        const unsigned gstep = 148u * (unsigned)(i + 1);
        const unsigned lstep = 32u * (unsigned)(i + 1);

        // GEMM1: hidden @ q_w[:,1024:]^T  (needs ln_fin(i-1))
        wait_ge(&g_lnc[2], 32u * (unsigned)i);
        {
            const unsigned* segs[4] = { g_hidp, g_hidp, g_hidp, g_hidp };
            gemm_mma<16>(dyn, segs, 10, 1024, g_qwp, 128, 64, 1024, 1024, 16);
        }
        signal(&g_gmc[0]);
        prefetch2<32>(dyn, g_intwp, 256, 64, 4096, 3072, 8);
        if (is_ln) {
            wait_ge(&g_gmc[0], gstep);
            ln_attn_phase(sml, g_p1 + (size_t)i * BB * 1024, qn_g, qn_b, i);
            signal(&g_lnc[0]);
        }

        // GEMM2: [q|attn|hidden] @ int_w[:,1024:]^T
        wait_ge(&g_lnc[0], lstep);
        {
            const unsigned* segs[4] = { g_qp, g_attnp, g_hidp, g_hidp };
            gemm_mma<32>(dyn, segs, 10, 1024, g_intwp, 256, 64, 4096, 3072, 8);
        }
        signal(&g_gmc[1]);
        prefetch2<32>(dyn, g_finwp, 256, 0, 3072, 4096, 8);
        if (is_ln) {
            wait_ge(&g_gmc[1], gstep);
            ln_phase(sml, g_p2 + (size_t)i * BB * 4096, 0, intn_g, intn_b, 4096, 8, 1, i, out_states);
            signal(&g_lnc[1]);
        }

        // GEMM3: inter @ fin_w^T
        wait_ge(&g_lnc[1], lstep);
        {
            const unsigned* segs[4] = { g_interp, g_interp, g_interp, g_interp };
            gemm_mma<32>(dyn, segs, 12, 4096, g_finwp, 256, 0, 3072, 4096, 8);
        }
        signal(&g_gmc[2]);
        prefetch2<16>(dyn, g_qwp, 128, 64, 1024, 1024, 16);
        if (is_ln) {
            wait_ge(&g_gmc[2], gstep);
            ln_phase(sml, 0, fin_b, fn_g, fn_b, 3072, 8, 2, i, out_states);
            signal(&g_lnc[2]);
        }
    }
}

// ---------------- weight convert (all four in one kernel) ----------------
__device__ __forceinline__ void convert_range(const float* __restrict__ w,
                                              unsigned* __restrict__ wf, int total, int kshift) {
    const int K = 1 << kshift;
    const int halfK = K >> 1;
    const int pairs = total >> 1;
    for (int i = blockIdx.x * 256 + threadIdx.x; i < pairs; i += gridDim.x * 256) {
        int kp = i & (halfK - 1);
        int n  = i >> (kshift - 1);
        int k  = kp << 1;
        unsigned p0 = packsplit(w[((size_t)n << kshift) + k]);
        unsigned p1 = packsplit(w[((size_t)n << kshift) + k + 1]);
        unsigned bh = prmt(p0, p1, 0x5410);
        unsigned bl = prmt(p0, p1, 0x7632);
        int n8 = n >> 3, g = n & 7;
        int k16 = k >> 4, kr = k & 15;
        int j = kr >> 1, t = j & 3, half = j >> 2;
        size_t base = (((size_t)n8 * (K >> 4) + k16) * 32 + g * 4 + t) * 4;
        wf[base + half]     = bh;
        wf[base + 2 + half] = bl;
    }
}
__global__ void k_convert_all(const float* __restrict__ q_w, const float* __restrict__ int_w,
                              const float* __restrict__ fin_w, const float* __restrict__ dec_w) {
    convert_range(q_w,   g_qwp,   1024 * 2048, 11);
    convert_range(int_w, g_intwp, 4096 * 4096, 12);
    convert_range(fin_w, g_finwp, 3072 * 4096, 12);
    convert_range(dec_w, g_decwp, VV * 1024,   10);
}

// ---------------- embedding gather (packed) ----------------
__global__ void k_embed(const int* __restrict__ obs, const float* __restrict__ enc_w) {
    int sb = blockIdx.x;
    int tok = obs[sb];
    const float4* src = (const float4*)(enc_w + (size_t)tok * 1024);
    float4 v = src[threadIdx.x];
    uint4 p = make_uint4(packsplit(v.x), packsplit(v.y), packsplit(v.z), packsplit(v.w));
    ((uint4*)(g_embp + (size_t)sb * 1024))[threadIdx.x] = p;
}

// ---------------- init ----------------
__global__ void k_init(const float* __restrict__ hidden_init,
                       const float* __restrict__ kci,
                       const float* __restrict__ vci,
                       float* __restrict__ out_states) {
    if (blockIdx.x == 0 && threadIdx.x == 0) {
        g_gmc[0] = g_gmc[1] = g_gmc[2] = 0;
        g_lnc[0] = g_lnc[1] = g_lnc[2] = 0;
    }
    int idx = blockIdx.x * 256 + threadIdx.x;
    float4 h = ((const float4*)hidden_init)[idx];
    ((float4*)out_states)[idx] = h;
    ((float4*)g_keys)[idx] = ((const float4*)kci)[idx];
    ((float4*)g_vals)[idx] = ((const float4*)vci)[idx];
    uint4 p = make_uint4(packsplit(h.x), packsplit(h.y), packsplit(h.z), packsplit(h.w));
    ((uint4*)g_hidp)[idx] = p;
}

// ---------------- big-M GEMM: out[4096][ld] = A[4096 x 1024] @ Wf^T + bias ----------------
__global__ void __launch_bounds__(512, 1) k_bigmm(const unsigned* __restrict__ A,
                                                  const unsigned* __restrict__ Wf,
                                                  int K16tot, int woff,
                                                  const float* __restrict__ bias,
                                                  float* __restrict__ out, int ldout) {
    const int m0 = blockIdx.x * 128;
    const int n0 = blockIdx.y * 256;
    const int warp = threadIdx.x >> 5, lane = threadIdx.x & 31;
    const int g = lane >> 2, t = lane & 3;
    const int mb = m0 + (warp & 3) * 32;
    const int nb = n0 + (warp >> 2) * 64;
    const int n8b = nb >> 3;

    float acc[2][8][4];
    #pragma unroll
    for (int mt = 0; mt < 2; mt++)
        #pragma unroll
        for (int ni = 0; ni < 8; ni++)
            #pragma unroll
            for (int e = 0; e < 4; e++) acc[mt][ni][e] = 0.f;

    for (int k0 = 0; k0 < 1024; k0 += 16) {
        unsigned ahi[2][4], alo[2][4];
        #pragma unroll
        for (int mt = 0; mt < 2; mt++) {
            const unsigned* x0 = A + (size_t)(mb + mt * 16 + g) * 1024 + k0 + t * 2;
            const unsigned* x8 = x0 + 8 * 1024;
            uint2 p0 = *(const uint2*)x0;
            uint2 p1 = *(const uint2*)x8;
            uint2 p2 = *(const uint2*)(x0 + 8);
            uint2 p3 = *(const uint2*)(x8 + 8);
            ahi[mt][0] = prmt(p0.x, p0.y, 0x5410); alo[mt][0] = prmt(p0.x, p0.y, 0x7632);
            ahi[mt][1] = prmt(p1.x, p1.y, 0x5410); alo[mt][1] = prmt(p1.x, p1.y, 0x7632);
            ahi[mt][2] = prmt(p2.x, p2.y, 0x5410); alo[mt][2] = prmt(p2.x, p2.y, 0x7632);
            ahi[mt][3] = prmt(p3.x, p3.y, 0x5410); alo[mt][3] = prmt(p3.x, p3.y, 0x7632);
        }
        #pragma unroll
        for (int ni = 0; ni < 8; ni++) {
            const uint4 q = *(const uint4*)(Wf + (((size_t)(n8b + ni) * K16tot + woff + (k0 >> 4)) * 32 + lane) * 4);
            #pragma unroll
            for (int mt = 0; mt < 2; mt++) {
                mma16816(acc[mt][ni], ahi[mt], q.x, q.y);
                mma16816(acc[mt][ni], ahi[mt], q.z, q.w);
                mma16816(acc[mt][ni], alo[mt], q.x, q.y);
            }
        }
    }
    #pragma unroll
    for (int mt = 0; mt < 2; mt++) {
        int m = mb + mt * 16 + g;
        #pragma unroll
        for (int ni = 0; ni < 8; ni++) {
            int n = nb + ni * 8 + t * 2;
            float bx = bias[n], by = bias[n + 1];
            *(float2*)&out[(size_t)m * ldout + n]       = make_float2(acc[mt][ni][0] + bx, acc[mt][ni][1] + by);
            *(float2*)&out[(size_t)(m + 8) * ldout + n] = make_float2(acc[mt][ni][2] + bx, acc[mt][ni][3] + by);
        }
    }
}

// ---------------- launch ----------------
extern "C" void kernel_launch(void* const* d_in, const int* in_sizes, int n_in,
                              void* d_out, int out_size) {
    const int*   obs         = (const int*)d_in[0];
    const float* hidden_init = (const float*)d_in[1];
    const float* kci         = (const float*)d_in[2];
    const float* vci         = (const float*)d_in[3];
    const float* enc_w       = (const float*)d_in[4];
    const float* q_w         = (const float*)d_in[5];
    const float* q_b         = (const float*)d_in[6];
    const float* qn_g        = (const float*)d_in[7];
    const float* qn_b        = (const float*)d_in[8];
    const float* int_w       = (const float*)d_in[9];
    const float* int_b       = (const float*)d_in[10];
    const float* intn_g      = (const float*)d_in[11];
    const float* intn_b      = (const float*)d_in[12];
    const float* fin_w       = (const float*)d_in[13];
    const float* fin_b       = (const float*)d_in[14];
    const float* fn_g        = (const float*)d_in[15];
    const float* fn_b        = (const float*)d_in[16];
    const float* dec_w       = (const float*)d_in[17];
    const float* dec_b       = (const float*)d_in[18];

    float* out        = (float*)d_out;
    float* out_states = out + (size_t)SS * BB * VV;

    unsigned* qwp;  cudaGetSymbolAddress((void**)&qwp,  g_qwp);
    unsigned* iwp;  cudaGetSymbolAddress((void**)&iwp,  g_intwp);
    unsigned* dwp;  cudaGetSymbolAddress((void**)&dwp,  g_decwp);
    unsigned* emb;  cudaGetSymbolAddress((void**)&emb,  g_embp);
    unsigned* spk;  cudaGetSymbolAddress((void**)&spk,  g_spack);
    float* p1;      cudaGetSymbolAddress((void**)&p1,   g_p1);
    float* p2;      cudaGetSymbolAddress((void**)&p2,   g_p2);

    const int smem_bytes = (W_U32 + A_U32) * 4 + (int)sizeof(SmemL);
    static int smem_set = 0;
    if (!smem_set) {
        cudaFuncSetAttribute(k_seq, cudaFuncAttributeMaxDynamicSharedMemorySize, smem_bytes);
        smem_set = 1;
    }

    k_convert_all<<<4096, 256>>>(q_w, int_w, fin_w, dec_w);
    k_embed<<<SS * BB, 256>>>(obs, enc_w);
    k_init<<<32, 256>>>(hidden_init, kci, vci, out_states);

    // precompute embedding contributions (bias folded)
    k_bigmm<<<dim3(32, 4),  512>>>(emb, qwp, 128, 0, q_b,   p1, 1024);
    k_bigmm<<<dim3(32, 16), 512>>>(emb, iwp, 256, 0, int_b, p2, 4096);

    k_seq<<<NBLK, 512, smem_bytes>>>(qn_g, qn_b, intn_g, intn_b,
                                     fin_b, fn_g, fn_b, out_states);

    // decoder
    k_bigmm<<<dim3(32, VV / 256), 512>>>(spk, dwp, 64, 0, dec_b, out, VV);
}